// round 1
// baseline (speedup 1.0000x reference)
#include <cuda_runtime.h>
#include <math.h>

#define NN_N   512
#define FB     256
#define DD     64
#define HH     4
#define HD     128
#define HHD    512
#define LAYERS 4
#define KDIM   100
#define NPAIR  (NN_N*NN_N)
#define EPSV   1e-5f

typedef unsigned long long ull;

// ---------------- device scratch (static globals: allocation-free) ----------------
__device__ float g_bias0[NPAIR*DD];   // 64 MB  ping
__device__ float g_bias1[NPAIR*DD];   // 64 MB  pong
__device__ float g_diffs[HH*NPAIR];   // 4 MB   [h][n][m]
__device__ float g_x[NN_N*DD];
__device__ float g_b0[NN_N*DD];
__device__ float g_qkv[NN_N*3*HHD];   // [n][h*384 + {q:0,k:128,v:256} + d]
__device__ float g_vals[NN_N*HHD];

// ---------------- helpers ----------------
__device__ __forceinline__ ull pk2(float lo, float hi){
    ull r; asm("mov.b64 %0, {%1,%2};" : "=l"(r) : "f"(lo), "f"(hi)); return r;
}
__device__ __forceinline__ float2 upk2(ull v){
    float2 r; asm("mov.b64 {%0,%1}, %2;" : "=f"(r.x), "=f"(r.y) : "l"(v)); return r;
}
__device__ __forceinline__ void fma2(ull &d, ull a, ull b){
    asm("fma.rn.f32x2 %0, %1, %2, %3;" : "=l"(d) : "l"(a), "l"(b), "l"(d));
}
__device__ __forceinline__ float mishf(float x){
    // softplus = max(x,0) + log1p(exp(-|x|));  tanh(sp) = 1 - 2/(exp(2sp)+1)
    float sp = fmaxf(x, 0.f) + __logf(1.f + __expf(-fabsf(x)));
    float e  = __expf(2.f * sp);          // inf -> tanh = 1 (correct)
    float t  = 1.f - 2.f / (e + 1.f);
    return x * t;
}

// ---------------- K1: embeddings + LN1 ----------------
__global__ void k_embed(const float* __restrict__ nf, const float* __restrict__ am,
                        const float* __restrict__ eW, const float* __restrict__ eb,
                        const float* __restrict__ bW, const float* __restrict__ bbv,
                        const float* __restrict__ g1, const float* __restrict__ b1){
    int n = blockIdx.x, d = threadIdx.x;  // 64 threads
    float acc = eb[d];
    for (int f = 0; f < FB; f++) acc += nf[n*FB + f] * eW[f*DD + d];
    float b0 = bbv[d];
    for (int k = 0; k < KDIM; k++) b0 += am[n*KDIM + k] * bW[k*DD + d];
    g_b0[n*DD + d] = b0;
    __shared__ float s[DD];
    s[d] = acc; __syncthreads();
    float mu = 0.f;
    #pragma unroll
    for (int k = 0; k < DD; k++) mu += s[k];
    mu *= (1.f/DD);
    float var = 0.f;
    #pragma unroll
    for (int k = 0; k < DD; k++){ float dd = s[k]-mu; var += dd*dd; }
    var *= (1.f/DD);
    g_x[n*DD + d] = (acc - mu) * rsqrtf(var + EPSV) * g1[d] + b1[d];
}

// ---------------- K2: bias[n,m,:] = b0[m] - b0[n] ----------------
__global__ void k_biasinit(){
    long idx = (long)blockIdx.x * blockDim.x + threadIdx.x;   // NPAIR*DD threads
    int d = (int)(idx & 63);
    long pair = idx >> 6;
    int m = (int)(pair & 511);
    int n = (int)(pair >> 9);
    g_bias0[idx] = g_b0[m*DD + d] - g_b0[n*DD + d];
}

// ---------------- K3: qkv = x @ qkv_W + b (8 rows per block) ----------------
__global__ void __launch_bounds__(512,1)
k_qkv(const float* __restrict__ W, const float* __restrict__ b){
    int n0 = blockIdx.x * 8;
    __shared__ float xs[8*DD];
    int t = threadIdx.x;
    xs[t] = g_x[n0*DD + t];
    __syncthreads();
    for (int j = t; j < 3*HHD; j += 512){
        float acc[8];
        float bv = b[j];
        #pragma unroll
        for (int r = 0; r < 8; r++) acc[r] = bv;
        #pragma unroll 8
        for (int d = 0; d < DD; d++){
            float w = W[d*(3*HHD) + j];
            #pragma unroll
            for (int r = 0; r < 8; r++) acc[r] += xs[r*DD + d] * w;
        }
        #pragma unroll
        for (int r = 0; r < 8; r++) g_qkv[(long)(n0+r)*(3*HHD) + j] = acc[r];
    }
}

// ---------------- K4: THE big fused kernel -------------------------------------
// per block: 64 pair-rows.  GEMM1 [64x64]@[64x512] -> mish -> beS(smem) + diffs,
// GEMM2 [64x512]@[512x64] -> mish -> new bias.   f32x2 packed FMA throughout.
#define BE_SMEM (16384 + 131072 + 16384 + 1024)
__global__ void __launch_bounds__(512,1)
k_be(const float* __restrict__ dW, const float* __restrict__ db,
     const float* __restrict__ bW, const float* __restrict__ bb,
     int flip, int writeBias){
    extern __shared__ float sm[];
    float* biasS = sm;                    // [64][64]
    float* beS   = sm + 4096;             // [64][512]
    float* bWs   = sm + 4096 + 32768;     // [64][64] staging for bout_W chunk
    float* sqS   = bWs + 4096;            // [64][4]

    const float* bin  = flip ? g_bias1 : g_bias0;
    float*       bnew = flip ? g_bias0 : g_bias1;

    int t = threadIdx.x;
    long pair0 = (long)blockIdx.x * 64;

    {   // load 64x64 bias tile (coalesced float4)
        const float4* src = (const float4*)(bin + pair0*DD);
        float4* dst = (float4*)biasS;
        dst[t]       = src[t];
        dst[t + 512] = src[t + 512];
    }
    __syncthreads();

    int ty = t >> 6;          // 0..7   -> rows ty*8..ty*8+7
    int tx = t & 63;          // 0..63  -> cols tx*8..tx*8+7
    int r0 = ty * 8;
    int c0 = tx * 8;

    // ---- GEMM1: acc[i][k] packs column pairs (c0+2k, c0+2k+1) ----
    ull acc[8][4];
    #pragma unroll
    for (int i = 0; i < 8; i++)
        #pragma unroll
        for (int k = 0; k < 4; k++) acc[i][k] = 0ull;

    #pragma unroll 4
    for (int d = 0; d < DD; d++){
        const float* wrow = dW + d*HHD + c0;
        ulonglong2 wA = *(const ulonglong2*)wrow;        // cols c0..c0+3 packed
        ulonglong2 wB = *(const ulonglong2*)(wrow + 4);  // cols c0+4..c0+7
        #pragma unroll
        for (int i = 0; i < 8; i++){
            float av = biasS[(r0+i)*DD + d];             // broadcast LDS
            ull a2 = pk2(av, av);
            fma2(acc[i][0], a2, wA.x);
            fma2(acc[i][1], a2, wA.y);
            fma2(acc[i][2], a2, wB.x);
            fma2(acc[i][3], a2, wB.y);
        }
    }

    // ---- epilogue: +bias, mish, store beS, squared-norm partials ----
    int head = tx >> 4;   // cols c0..c0+7 all inside head = (tx*8)/128
    float2 dbv[4];
    #pragma unroll
    for (int k = 0; k < 4; k++) dbv[k] = *(const float2*)(db + c0 + 2*k);

    float ss[8];
    #pragma unroll
    for (int i = 0; i < 8; i++){
        float out[8]; float s = 0.f;
        #pragma unroll
        for (int k = 0; k < 4; k++){
            float2 v = upk2(acc[i][k]);
            float m0 = mishf(v.x + dbv[k].x);
            float m1 = mishf(v.y + dbv[k].y);
            out[2*k] = m0; out[2*k+1] = m1;
            s += m0*m0 + m1*m1;
        }
        float4* dst = (float4*)&beS[(r0+i)*HHD + c0];
        dst[0] = make_float4(out[0], out[1], out[2], out[3]);
        dst[1] = make_float4(out[4], out[5], out[6], out[7]);
        ss[i] = s;
    }
    // reduce squared sums over the 16 lanes of each head group
    #pragma unroll
    for (int i = 0; i < 8; i++){
        float s = ss[i];
        s += __shfl_xor_sync(0xffffffffu, s, 1);
        s += __shfl_xor_sync(0xffffffffu, s, 2);
        s += __shfl_xor_sync(0xffffffffu, s, 4);
        s += __shfl_xor_sync(0xffffffffu, s, 8);
        if ((t & 15) == 0) sqS[(r0+i)*4 + head] = s;
    }
    __syncthreads();
    if (t < 256){
        int r = t >> 2, h = t & 3;
        g_diffs[(long)h*NPAIR + pair0 + r] = sqrtf(sqS[r*4 + h]);
    }

    // ---- GEMM2: bias_new = mish(beS @ bout_W + bb) ----
    if (writeBias){
        int icol = t & 63;     // output column
        int rg   = t >> 6;     // rows rg*8 .. rg*8+7
        ull acc2[8];
        #pragma unroll
        for (int ii = 0; ii < 8; ii++) acc2[ii] = 0ull;

        for (int jc = 0; jc < HHD; jc += 64){
            __syncthreads();
            {   // stage bout_W rows jc..jc+63 (contiguous 16 KB)
                const float4* s4 = (const float4*)(bW + jc*DD);
                float4* d4 = (float4*)bWs;
                d4[t]       = s4[t];
                d4[t + 512] = s4[t + 512];
            }
            __syncthreads();
            #pragma unroll 4
            for (int j = 0; j < 64; j += 4){
                float w0 = bWs[(j+0)*DD + icol];
                float w1 = bWs[(j+1)*DD + icol];
                float w2 = bWs[(j+2)*DD + icol];
                float w3 = bWs[(j+3)*DD + icol];
                ull wp0 = pk2(w0, w1);
                ull wp1 = pk2(w2, w3);
                #pragma unroll
                for (int ii = 0; ii < 8; ii++){
                    // be[row][j..j+3] as two packed f32x2 (zero-cost reinterpret)
                    ulonglong2 bq = *(const ulonglong2*)&beS[(rg*8+ii)*HHD + jc + j];
                    fma2(acc2[ii], bq.x, wp0);   // lanes hold partial sums over j,j+1
                    fma2(acc2[ii], bq.y, wp1);   // and j+2,j+3 — merged at the end
                }
            }
        }
        float bbv = bb[icol];
        #pragma unroll
        for (int ii = 0; ii < 8; ii++){
            float2 v = upk2(acc2[ii]);
            float val = v.x + v.y + bbv;
            bnew[(pair0 + rg*8 + ii)*DD + icol] = mishf(val);
        }
    }
}

// ---------------- K5: attention (logits + softmax + attn@v), per (head, 16-row tile) ----
__global__ void __launch_bounds__(512,1) k_attn(float scale){
    int h  = blockIdx.y;
    int n0 = blockIdx.x * 16;
    __shared__ float qS[16*HD];      // 8 KB
    __shared__ float lg[16*NN_N];    // 32 KB
    int t = threadIdx.x;

    for (int idx = t; idx < 16*HD; idx += 512){
        int nn = idx >> 7, d = idx & 127;
        qS[idx] = g_qkv[(long)(n0+nn)*(3*HHD) + h*384 + d];
    }
    __syncthreads();

    {   // logits: thread = key index m
        int m = t;
        float acc[16];
        #pragma unroll
        for (int nn = 0; nn < 16; nn++) acc[nn] = 0.f;
        const float* kp = g_qkv + (long)m*(3*HHD) + h*384 + 128;
        #pragma unroll 4
        for (int d = 0; d < HD; d += 4){
            float4 kv = *(const float4*)(kp + d);
            #pragma unroll
            for (int nn = 0; nn < 16; nn++){
                float4 qv = *(const float4*)&qS[nn*HD + d];
                acc[nn] += qv.x*kv.x + qv.y*kv.y + qv.z*kv.z + qv.w*kv.w;
            }
        }
        const float* dp = g_diffs + (long)h*NPAIR + (long)n0*NN_N + m;
        #pragma unroll
        for (int nn = 0; nn < 16; nn++)
            lg[nn*NN_N + m] = acc[nn]*scale + dp[(long)nn*NN_N];
    }
    __syncthreads();

    {   // softmax per row (32 lanes per row)
        int row = t >> 5, lane = t & 31;
        float* Lr = lg + row*NN_N;
        float mx = -1e30f;
        for (int m = lane; m < NN_N; m += 32) mx = fmaxf(mx, Lr[m]);
        #pragma unroll
        for (int o = 16; o; o >>= 1) mx = fmaxf(mx, __shfl_xor_sync(0xffffffffu, mx, o));
        float sum = 0.f;
        for (int m = lane; m < NN_N; m += 32){
            float e = __expf(Lr[m] - mx); Lr[m] = e; sum += e;
        }
        #pragma unroll
        for (int o = 16; o; o >>= 1) sum += __shfl_xor_sync(0xffffffffu, sum, o);
        float inv = 1.f / sum;
        for (int m = lane; m < NN_N; m += 32) Lr[m] *= inv;
    }
    __syncthreads();

    {   // vals = attn @ v
        int d = t & 127, ng = t >> 7;          // 4 rows per thread
        float acc[4] = {0.f, 0.f, 0.f, 0.f};
        const float* vp = g_qkv + h*384 + 256 + d;
        #pragma unroll 4
        for (int m = 0; m < NN_N; m++){
            float vv = vp[(long)m*(3*HHD)];
            #pragma unroll
            for (int k = 0; k < 4; k++) acc[k] += lg[(ng*4+k)*NN_N + m] * vv;
        }
        #pragma unroll
        for (int k = 0; k < 4; k++)
            g_vals[(long)(n0 + ng*4 + k)*HHD + h*HD + d] = acc[k];
    }
}

// ---------------- K5b: x = LN2(x + vals @ o_W + o_b) ----------------
__global__ void k_oln(const float* __restrict__ oW, const float* __restrict__ ob,
                      const float* __restrict__ g2, const float* __restrict__ b2){
    int n = blockIdx.x, i = threadIdx.x;   // 64 threads
    const float* vr = g_vals + (long)n*HHD;
    float a0 = 0.f, a1 = 0.f;
    #pragma unroll 4
    for (int j = 0; j < HHD; j += 2){
        a0 += vr[j]   * oW[j*DD + i];
        a1 += vr[j+1] * oW[(j+1)*DD + i];
    }
    float xv = g_x[n*DD + i] + a0 + a1 + ob[i];
    __shared__ float s[DD];
    s[i] = xv; __syncthreads();
    float mu = 0.f;
    #pragma unroll
    for (int k = 0; k < DD; k++) mu += s[k];
    mu *= (1.f/DD);
    float var = 0.f;
    #pragma unroll
    for (int k = 0; k < DD; k++){ float dd = s[k]-mu; var += dd*dd; }
    var *= (1.f/DD);
    g_x[n*DD + i] = (xv - mu) * rsqrtf(var + EPSV) * g2[i] + b2[i];
}

// ---------------- K6: out = x @ out_W + out_b ----------------
__global__ void k_out(const float* __restrict__ W, const float* __restrict__ bo,
                      float* __restrict__ out){
    int n = threadIdx.x;                   // <<<1,512>>>
    float acc = bo[0];
    #pragma unroll
    for (int d = 0; d < DD; d++) acc += g_x[n*DD + d] * W[d];
    out[n] = acc;
}

// ---------------- launcher ----------------
extern "C" void kernel_launch(void* const* d_in, const int* in_sizes, int n_in,
                              void* d_out, int out_size){
    const float* nf    = (const float*)d_in[0];
    const float* amds  = (const float*)d_in[1];
    const float* embW  = (const float*)d_in[2];
    const float* embb  = (const float*)d_in[3];
    const float* bembW = (const float*)d_in[4];
    const float* bembb = (const float*)d_in[5];
    const float* ln1g  = (const float*)d_in[6];
    const float* ln1b  = (const float*)d_in[7];
    const float* ln2g  = (const float*)d_in[8];
    const float* ln2b  = (const float*)d_in[9];
    const float* qkvW  = (const float*)d_in[10];
    const float* qkvb  = (const float*)d_in[11];
    const float* diffW = (const float*)d_in[12];
    const float* diffb = (const float*)d_in[13];
    const float* oW    = (const float*)d_in[14];
    const float* ob    = (const float*)d_in[15];
    const float* boutW = (const float*)d_in[16];
    const float* boutb = (const float*)d_in[17];
    const float* outW  = (const float*)d_in[18];
    const float* outb  = (const float*)d_in[19];

    cudaFuncSetAttribute(k_be, cudaFuncAttributeMaxDynamicSharedMemorySize, BE_SMEM);

    k_embed<<<NN_N, DD>>>(nf, amds, embW, embb, bembW, bembb, ln1g, ln1b);
    k_biasinit<<<NPAIR*DD/512, 512>>>();

    float scale = 1.f / sqrtf((float)HD);
    for (int l = 0; l < LAYERS; l++){
        k_qkv<<<NN_N/8, 512>>>(qkvW + (long)l*DD*3*HHD, qkvb + l*3*HHD);
        k_be<<<NPAIR/64, 512, BE_SMEM>>>(diffW + (long)l*DD*HHD, diffb + l*HHD,
                                         boutW + (long)l*HHD*DD, boutb + l*DD,
                                         l & 1, (l < LAYERS-1) ? 1 : 0);
        k_attn<<<dim3(NN_N/16, HH), 512>>>(scale);
        k_oln<<<NN_N, DD>>>(oW + (long)l*HHD*DD, ob + l*DD, ln2g, ln2b);
    }
    k_out<<<1, NN_N>>>(outW, outb, (float*)d_out);
}